// round 7
// baseline (speedup 1.0000x reference)
#include <cuda_runtime.h>
#include <math.h>

#define NB    256   // batch*windows
#define DIMC  256
#define HEADS 8
#define DH    32
#define NQ    256
#define NK    576

// ---------------- scratch (static __device__: no allocation) ----------------
__device__ float g_q[16777216];     // (B*Nq, 256)  q-proj, pre-scaled
__device__ float g_kv[75497472];    // (B*Nk, 512)  [k | v] per token
__device__ float g_bias[1179648];   // (H, Nq, Nk)  gathered rel-pos bias
__device__ float g_att[16777216];   // (B*Nq, 256)  attention output

// ---------------- bias gather ----------------
__global__ __launch_bounds__(256) void bias_gather_kernel(
    const float* __restrict__ table, const int* __restrict__ rel,
    float* __restrict__ out)
{
    int idx = blockIdx.x * 256 + threadIdx.x;      // < Nq*Nk = 147456
    int r = rel[idx];
    const float* t = table + r * HEADS;
    #pragma unroll
    for (int h = 0; h < HEADS; ++h)
        out[h * (NQ * NK) + idx] = t[h];
}

// ---------------- 128x128x8 double-buffered SGEMM, K fixed = 256 ------------
// C[row, col] = (sum_k A[row,k]*W[k,col] + bias[col]) * scale
__global__ __launch_bounds__(256) void sgemm_bias_kernel(
    const float* __restrict__ A, const float* __restrict__ W,
    const float* __restrict__ bias, float* __restrict__ C,
    int N, float scale)
{
    const int K = 256;
    __shared__ float As[2][8][132];   // transposed: As[k][row], padded
    __shared__ float Bs[2][8][132];   // Bs[k][col], padded

    int tid = threadIdx.x;
    const float* Ab = A + (size_t)blockIdx.y * 128 * K;
    const float* Wb = W + blockIdx.x * 128;

    int arow = tid >> 1;           // 0..127
    int acol = (tid & 1) << 2;     // 0 or 4
    int brow = tid >> 5;           // 0..7
    int bcol = (tid & 31) << 2;    // 0..124
    int ty = tid >> 4, tx = tid & 15;

    float acc[8][8];
    #pragma unroll
    for (int i = 0; i < 8; ++i)
        #pragma unroll
        for (int j = 0; j < 8; ++j) acc[i][j] = 0.f;

    float4 a_reg = *(const float4*)(Ab + (size_t)arow * K + acol);
    float4 b_reg = *(const float4*)(Wb + (size_t)brow * N + bcol);
    As[0][acol + 0][arow] = a_reg.x;
    As[0][acol + 1][arow] = a_reg.y;
    As[0][acol + 2][arow] = a_reg.z;
    As[0][acol + 3][arow] = a_reg.w;
    *(float4*)&Bs[0][brow][bcol] = b_reg;
    __syncthreads();

    int s = 0;
    #pragma unroll 1
    for (int kt = 0; kt < K / 8; ++kt) {
        if (kt + 1 < K / 8) {
            a_reg = *(const float4*)(Ab + (size_t)arow * K + (kt + 1) * 8 + acol);
            b_reg = *(const float4*)(Wb + (size_t)((kt + 1) * 8 + brow) * N + bcol);
        }
        #pragma unroll
        for (int k = 0; k < 8; ++k) {
            float4 a0 = *(float4*)&As[s][k][ty * 8];
            float4 a1 = *(float4*)&As[s][k][ty * 8 + 4];
            float4 b0 = *(float4*)&Bs[s][k][tx * 8];
            float4 b1 = *(float4*)&Bs[s][k][tx * 8 + 4];
            float av[8] = {a0.x, a0.y, a0.z, a0.w, a1.x, a1.y, a1.z, a1.w};
            float bv[8] = {b0.x, b0.y, b0.z, b0.w, b1.x, b1.y, b1.z, b1.w};
            #pragma unroll
            for (int i = 0; i < 8; ++i)
                #pragma unroll
                for (int j = 0; j < 8; ++j)
                    acc[i][j] += av[i] * bv[j];
        }
        if (kt + 1 < K / 8) {
            int ns = s ^ 1;
            As[ns][acol + 0][arow] = a_reg.x;
            As[ns][acol + 1][arow] = a_reg.y;
            As[ns][acol + 2][arow] = a_reg.z;
            As[ns][acol + 3][arow] = a_reg.w;
            *(float4*)&Bs[ns][brow][bcol] = b_reg;
            __syncthreads();
            s = ns;
        }
    }

    int row0 = blockIdx.y * 128 + ty * 8;
    int col0 = blockIdx.x * 128 + tx * 8;
    float bb[8];
    *(float4*)&bb[0] = *(const float4*)(bias + col0);
    *(float4*)&bb[4] = *(const float4*)(bias + col0 + 4);
    #pragma unroll
    for (int i = 0; i < 8; ++i) {
        float4 o0, o1;
        o0.x = (acc[i][0] + bb[0]) * scale;
        o0.y = (acc[i][1] + bb[1]) * scale;
        o0.z = (acc[i][2] + bb[2]) * scale;
        o0.w = (acc[i][3] + bb[3]) * scale;
        o1.x = (acc[i][4] + bb[4]) * scale;
        o1.y = (acc[i][5] + bb[5]) * scale;
        o1.z = (acc[i][6] + bb[6]) * scale;
        o1.w = (acc[i][7] + bb[7]) * scale;
        *(float4*)(C + (size_t)(row0 + i) * N + col0)     = o0;
        *(float4*)(C + (size_t)(row0 + i) * N + col0 + 4) = o1;
    }
}

// ---------------- fused attention: S = QK^T + bias; softmax; O = P V --------
#define SPAD 584
#define ATT_SMEM_FLOATS (32 * 36 + 64 * 36 + 32 * SPAD)
#define ATT_SMEM (ATT_SMEM_FLOATS * 4)

__global__ __launch_bounds__(256) void attn_kernel(
    const float* __restrict__ qp,    // (B*Nq, 256), already *scale
    const float* __restrict__ kvp,   // (B*Nk, 512)
    const float* __restrict__ bias,  // (H, Nq, Nk)
    float* __restrict__ outp)        // (B*Nq, 256)
{
    extern __shared__ float sm[];
    float* qt = sm;                   // [32(d)][36(i)]  q transposed
    float* kt = sm + 32 * 36;         // pass1: [32(d)][68(j)] ; pass3: v [64(j)][36(d)]
    float* S  = sm + 32 * 36 + 64 * 36; // [32][SPAD]

    int tid = threadIdx.x;
    int i0 = blockIdx.x * 32;
    int h  = blockIdx.y;
    int b  = blockIdx.z;

    const float* qbase = qp + ((size_t)b * NQ + i0) * DIMC + h * DH;
    const float* kbase = kvp + (size_t)b * NK * (2 * DIMC) + h * DH;
    const float* vbase = kbase + DIMC;
    const float* bbase = bias + ((size_t)h * NQ + i0) * NK;

    // load q tile, transposed (d-major)
    {
        int i  = tid >> 3;
        int d4 = (tid & 7) << 2;
        float4 v = *(const float4*)(qbase + (size_t)i * DIMC + d4);
        qt[(d4 + 0) * 36 + i] = v.x;
        qt[(d4 + 1) * 36 + i] = v.y;
        qt[(d4 + 2) * 36 + i] = v.z;
        qt[(d4 + 3) * 36 + i] = v.w;
    }

    int ty  = tid >> 5;          // 0..7  -> q rows ty*4..+3
    int tx  = tid & 31;          // k cols tx*2..+1 within chunk
    int lj  = tid >> 3;          // loader row 0..31
    int ld4 = (tid & 7) << 2;    // loader d 0..28

    // -------- pass 1: scores --------
    #pragma unroll 1
    for (int kc = 0; kc < NK; kc += 64) {
        __syncthreads();   // q visible (1st iter) / prev compute done before kt overwrite
        #pragma unroll
        for (int jj = 0; jj < 2; ++jj) {
            int jr = lj + jj * 32;
            float4 v = *(const float4*)(kbase + (size_t)(kc + jr) * (2 * DIMC) + ld4);
            kt[(ld4 + 0) * 68 + jr] = v.x;
            kt[(ld4 + 1) * 68 + jr] = v.y;
            kt[(ld4 + 2) * 68 + jr] = v.z;
            kt[(ld4 + 3) * 68 + jr] = v.w;
        }
        __syncthreads();

        float a00 = 0, a01 = 0, a10 = 0, a11 = 0, a20 = 0, a21 = 0, a30 = 0, a31 = 0;
        #pragma unroll
        for (int d = 0; d < 32; ++d) {
            float4 a  = *(float4*)(qt + d * 36 + ty * 4);
            float2 bv = *(float2*)(kt + d * 68 + tx * 2);
            a00 += a.x * bv.x; a01 += a.x * bv.y;
            a10 += a.y * bv.x; a11 += a.y * bv.y;
            a20 += a.z * bv.x; a21 += a.z * bv.y;
            a30 += a.w * bv.x; a31 += a.w * bv.y;
        }
        int col = kc + tx * 2;
        float2 b0 = *(const float2*)(bbase + (size_t)(ty * 4 + 0) * NK + col);
        float2 b1 = *(const float2*)(bbase + (size_t)(ty * 4 + 1) * NK + col);
        float2 b2 = *(const float2*)(bbase + (size_t)(ty * 4 + 2) * NK + col);
        float2 b3 = *(const float2*)(bbase + (size_t)(ty * 4 + 3) * NK + col);
        S[(ty * 4 + 0) * SPAD + col]     = a00 + b0.x;
        S[(ty * 4 + 0) * SPAD + col + 1] = a01 + b0.y;
        S[(ty * 4 + 1) * SPAD + col]     = a10 + b1.x;
        S[(ty * 4 + 1) * SPAD + col + 1] = a11 + b1.y;
        S[(ty * 4 + 2) * SPAD + col]     = a20 + b2.x;
        S[(ty * 4 + 2) * SPAD + col + 1] = a21 + b2.y;
        S[(ty * 4 + 3) * SPAD + col]     = a30 + b3.x;
        S[(ty * 4 + 3) * SPAD + col + 1] = a31 + b3.y;
    }
    __syncthreads();

    // -------- pass 2: softmax (1 warp -> 4 rows) --------
    {
        int w = tid >> 5, lane = tid & 31;
        #pragma unroll 1
        for (int rr = 0; rr < 4; ++rr) {
            float* Sr = S + (w * 4 + rr) * SPAD;
            float vals[18];
            float m = -1e30f;
            #pragma unroll
            for (int c = 0; c < 18; ++c) {
                vals[c] = Sr[lane + c * 32];
                m = fmaxf(m, vals[c]);
            }
            #pragma unroll
            for (int off = 16; off; off >>= 1)
                m = fmaxf(m, __shfl_xor_sync(0xffffffffu, m, off));
            float ssum = 0.f;
            #pragma unroll
            for (int c = 0; c < 18; ++c) {
                vals[c] = __expf(vals[c] - m);
                ssum += vals[c];
            }
            #pragma unroll
            for (int off = 16; off; off >>= 1)
                ssum += __shfl_xor_sync(0xffffffffu, ssum, off);
            float inv = 1.0f / ssum;
            #pragma unroll
            for (int c = 0; c < 18; ++c)
                Sr[lane + c * 32] = vals[c] * inv;
        }
    }

    // -------- pass 3: O = P @ V --------
    {
        float* vsm = kt;            // reuse: [64(j)][36(d)]
        int i  = tid >> 3;          // out row 0..31
        int d4 = (tid & 7) << 2;    // out col group
        float ax = 0, ay = 0, az = 0, aw = 0;
        #pragma unroll 1
        for (int kc = 0; kc < NK; kc += 64) {
            __syncthreads();  // softmax done (1st iter) / prev compute done
            #pragma unroll
            for (int jj = 0; jj < 2; ++jj) {
                int jr = lj + jj * 32;
                *(float4*)(vsm + jr * 36 + ld4) =
                    *(const float4*)(vbase + (size_t)(kc + jr) * (2 * DIMC) + ld4);
            }
            __syncthreads();
            #pragma unroll 8
            for (int j = 0; j < 64; ++j) {
                float p  = S[i * SPAD + kc + j];
                float4 v = *(float4*)(vsm + j * 36 + d4);
                ax += p * v.x; ay += p * v.y; az += p * v.z; aw += p * v.w;
            }
        }
        float4 o; o.x = ax; o.y = ay; o.z = az; o.w = aw;
        *(float4*)(outp + ((size_t)b * NQ + i0 + i) * DIMC + h * DH + d4) = o;
    }
}

// ---------------- launcher ----------------
extern "C" void kernel_launch(void* const* d_in, const int* in_sizes, int n_in,
                              void* d_out, int out_size)
{
    (void)in_sizes; (void)n_in; (void)out_size;
    const float* q_w    = (const float*)d_in[0];
    const float* kv_w   = (const float*)d_in[1];
    const float* q_W    = (const float*)d_in[2];
    const float* q_b    = (const float*)d_in[3];
    const float* kv_W   = (const float*)d_in[4];
    const float* kv_b   = (const float*)d_in[5];
    const float* proj_W = (const float*)d_in[6];
    const float* proj_b = (const float*)d_in[7];
    const float* btab   = (const float*)d_in[8];
    const int*   ridx   = (const int*)d_in[9];
    float* out = (float*)d_out;

    float *gq, *gkv, *gb, *ga;
    cudaGetSymbolAddress((void**)&gq,  g_q);
    cudaGetSymbolAddress((void**)&gkv, g_kv);
    cudaGetSymbolAddress((void**)&gb,  g_bias);
    cudaGetSymbolAddress((void**)&ga,  g_att);

    cudaFuncSetAttribute(attn_kernel,
                         cudaFuncAttributeMaxDynamicSharedMemorySize, ATT_SMEM);

    // 1) relative-position bias gather -> (H, Nq, Nk)
    bias_gather_kernel<<<(NQ * NK) / 256, 256>>>(btab, ridx, gb);

    // 2) kv projection: (B*Nk,256) @ (256,512) + b
    sgemm_bias_kernel<<<dim3(512 / 128, (NB * NK) / 128), 256>>>(
        kv_w, kv_W, kv_b, gkv, 512, 1.0f);

    // 3) q projection (pre-scaled by Dh^-0.5): (B*Nq,256) @ (256,256) + b
    sgemm_bias_kernel<<<dim3(256 / 128, (NB * NQ) / 128), 256>>>(
        q_w, q_W, q_b, gq, 256, 0.17677669529663687f);

    // 4) fused attention
    attn_kernel<<<dim3(NQ / 32, HEADS, NB), 256, ATT_SMEM>>>(gq, gkv, gb, ga);

    // 5) output projection: (B*Nq,256) @ (256,256) + b
    sgemm_bias_kernel<<<dim3(256 / 128, (NB * NQ) / 128), 256>>>(
        ga, proj_W, proj_b, out, 256, 1.0f);
}

// round 10
// speedup vs baseline: 1.2854x; 1.2854x over previous
#include <cuda_runtime.h>
#include <math.h>

#define NB    256   // batch*windows
#define DIMC  256
#define HEADS 8
#define DH    32
#define NQ    256
#define NK    576

// ---------------- scratch (static __device__: no allocation) ----------------
__device__ float g_q[16777216];     // (B*Nq, 256)  q-proj, pre-scaled
__device__ float g_kv[75497472];    // (B*Nk, 512)  [k | v] per token
__device__ float g_bias[1179648];   // (H, Nq, Nk)  gathered rel-pos bias
__device__ float g_att[16777216];   // (B*Nq, 256)  attention output

// ---------------- bias gather ----------------
__global__ __launch_bounds__(256) void bias_gather_kernel(
    const float* __restrict__ table, const int* __restrict__ rel,
    float* __restrict__ out)
{
    int idx = blockIdx.x * 256 + threadIdx.x;      // < Nq*Nk = 147456
    int r = rel[idx];
    const float* t = table + r * HEADS;
    #pragma unroll
    for (int h = 0; h < HEADS; ++h)
        out[h * (NQ * NK) + idx] = t[h];
}

// ---------------- tf32 helpers ----------------
__device__ __forceinline__ unsigned f2tf(float f)
{
    unsigned u;
    asm("cvt.rna.tf32.f32 %0, %1;" : "=r"(u) : "f"(f));
    return u;
}

__device__ __forceinline__ void mma_tf32(float c[4],
                                         const unsigned a[4],
                                         const unsigned b[2])
{
    asm volatile(
        "mma.sync.aligned.m16n8k8.row.col.f32.tf32.tf32.f32 "
        "{%0,%1,%2,%3}, {%4,%5,%6,%7}, {%8,%9}, {%0,%1,%2,%3};\n"
        : "+f"(c[0]), "+f"(c[1]), "+f"(c[2]), "+f"(c[3])
        : "r"(a[0]), "r"(a[1]), "r"(a[2]), "r"(a[3]),
          "r"(b[0]), "r"(b[1]));
}

// ------- tf32 tensor-core GEMM: C = (A @ W + bias) * scale, K fixed = 256 ---
// Block tile 128x128, kc=16 double-buffered. 8 warps = 2(M) x 4(N),
// warp tile 64x32 -> 4 m-frags x 4 n-frags of m16n8k8.
#define ASTRIDE 20    // words per A-row in smem (bank = 4*grp + qid: conflict-free)
#define BSTRIDE 136   // words per B-k-row in smem (bank = 8*qid + grp: conflict-free)

__global__ __launch_bounds__(256) void tf32_gemm_bias_kernel(
    const float* __restrict__ A, const float* __restrict__ W,
    const float* __restrict__ bias, float* __restrict__ C,
    int N, float scale)
{
    const int K = 256;
    __shared__ unsigned As[2][128 * ASTRIDE];
    __shared__ unsigned Bs[2][16 * BSTRIDE];

    int tid  = threadIdx.x;
    int lane = tid & 31, warp = tid >> 5;
    int wm = warp & 1, wn = warp >> 1;       // warp tile: rows wm*64, cols wn*32
    int grp = lane >> 2, qid = lane & 3;

    const float* Ab = A + (size_t)blockIdx.y * 128 * K;
    const float* Wb = W + blockIdx.x * 128;

    // loaders
    int ar  = tid >> 2;          // A rows ar, ar+64
    int aq  = tid & 3;           // A col quad (k) -> aq*4
    int bk  = tid >> 5;          // B k-rows bk, bk+8
    int bc4 = (tid & 31) << 2;   // B col start

    float acc[4][4][4];
    #pragma unroll
    for (int i = 0; i < 4; ++i)
        #pragma unroll
        for (int j = 0; j < 4; ++j)
            #pragma unroll
            for (int r = 0; r < 4; ++r) acc[i][j][r] = 0.f;

    float4 ra0 = *(const float4*)(Ab + (size_t)ar * K + aq * 4);
    float4 ra1 = *(const float4*)(Ab + (size_t)(ar + 64) * K + aq * 4);
    float4 rb0 = *(const float4*)(Wb + (size_t)bk * N + bc4);
    float4 rb1 = *(const float4*)(Wb + (size_t)(bk + 8) * N + bc4);

    {   // store chunk 0 (convert to tf32 bits)
        uint4 u;
        u = make_uint4(f2tf(ra0.x), f2tf(ra0.y), f2tf(ra0.z), f2tf(ra0.w));
        *(uint4*)&As[0][ar * ASTRIDE + aq * 4] = u;
        u = make_uint4(f2tf(ra1.x), f2tf(ra1.y), f2tf(ra1.z), f2tf(ra1.w));
        *(uint4*)&As[0][(ar + 64) * ASTRIDE + aq * 4] = u;
        u = make_uint4(f2tf(rb0.x), f2tf(rb0.y), f2tf(rb0.z), f2tf(rb0.w));
        *(uint4*)&Bs[0][bk * BSTRIDE + bc4] = u;
        u = make_uint4(f2tf(rb1.x), f2tf(rb1.y), f2tf(rb1.z), f2tf(rb1.w));
        *(uint4*)&Bs[0][(bk + 8) * BSTRIDE + bc4] = u;
    }
    __syncthreads();

    int s = 0;
    #pragma unroll 1
    for (int kc = 0; kc < K / 16; ++kc) {
        if (kc + 1 < K / 16) {
            int k0 = (kc + 1) * 16;
            ra0 = *(const float4*)(Ab + (size_t)ar * K + k0 + aq * 4);
            ra1 = *(const float4*)(Ab + (size_t)(ar + 64) * K + k0 + aq * 4);
            rb0 = *(const float4*)(Wb + (size_t)(k0 + bk) * N + bc4);
            rb1 = *(const float4*)(Wb + (size_t)(k0 + bk + 8) * N + bc4);
        }

        const unsigned* Ap = &As[s][0];
        const unsigned* Bp = &Bs[s][0];
        #pragma unroll
        for (int ks = 0; ks < 2; ++ks) {
            unsigned af[4][4], bf[4][2];
            #pragma unroll
            for (int mf = 0; mf < 4; ++mf) {
                int r0 = (wm * 64 + mf * 16 + grp) * ASTRIDE + ks * 8 + qid;
                af[mf][0] = Ap[r0];
                af[mf][1] = Ap[r0 + 8 * ASTRIDE];
                af[mf][2] = Ap[r0 + 4];
                af[mf][3] = Ap[r0 + 8 * ASTRIDE + 4];
            }
            #pragma unroll
            for (int nf = 0; nf < 4; ++nf) {
                int c0 = (ks * 8 + qid) * BSTRIDE + wn * 32 + nf * 8 + grp;
                bf[nf][0] = Bp[c0];
                bf[nf][1] = Bp[c0 + 4 * BSTRIDE];
            }
            #pragma unroll
            for (int mf = 0; mf < 4; ++mf)
                #pragma unroll
                for (int nf = 0; nf < 4; ++nf)
                    mma_tf32(acc[mf][nf], af[mf], bf[nf]);
        }

        if (kc + 1 < K / 16) {
            int ns = s ^ 1;
            uint4 u;
            u = make_uint4(f2tf(ra0.x), f2tf(ra0.y), f2tf(ra0.z), f2tf(ra0.w));
            *(uint4*)&As[ns][ar * ASTRIDE + aq * 4] = u;
            u = make_uint4(f2tf(ra1.x), f2tf(ra1.y), f2tf(ra1.z), f2tf(ra1.w));
            *(uint4*)&As[ns][(ar + 64) * ASTRIDE + aq * 4] = u;
            u = make_uint4(f2tf(rb0.x), f2tf(rb0.y), f2tf(rb0.z), f2tf(rb0.w));
            *(uint4*)&Bs[ns][bk * BSTRIDE + bc4] = u;
            u = make_uint4(f2tf(rb1.x), f2tf(rb1.y), f2tf(rb1.z), f2tf(rb1.w));
            *(uint4*)&Bs[ns][(bk + 8) * BSTRIDE + bc4] = u;
            __syncthreads();
            s = ns;
        }
    }

    // epilogue: c0/c1 at (row, col..col+1), c2/c3 at (row+8, col..col+1)
    int row0 = blockIdx.y * 128 + wm * 64;
    int col0 = blockIdx.x * 128 + wn * 32;
    #pragma unroll
    for (int mf = 0; mf < 4; ++mf) {
        int r = row0 + mf * 16 + grp;
        #pragma unroll
        for (int nf = 0; nf < 4; ++nf) {
            int c = col0 + nf * 8 + qid * 2;
            float bx = __ldg(bias + c);
            float by = __ldg(bias + c + 1);
            float2 o0, o1;
            o0.x = (acc[mf][nf][0] + bx) * scale;
            o0.y = (acc[mf][nf][1] + by) * scale;
            o1.x = (acc[mf][nf][2] + bx) * scale;
            o1.y = (acc[mf][nf][3] + by) * scale;
            *(float2*)(C + (size_t)r * N + c)       = o0;
            *(float2*)(C + (size_t)(r + 8) * N + c) = o1;
        }
    }
}

// ---------------- fused attention: S = QK^T + bias; softmax; O = P V --------
#define SPAD 584
#define ATT_SMEM_FLOATS (32 * 36 + 64 * 36 + 32 * SPAD)
#define ATT_SMEM (ATT_SMEM_FLOATS * 4)

__global__ __launch_bounds__(256) void attn_kernel(
    const float* __restrict__ qp,    // (B*Nq, 256), already *scale
    const float* __restrict__ kvp,   // (B*Nk, 512)
    const float* __restrict__ bias,  // (H, Nq, Nk)
    float* __restrict__ outp)        // (B*Nq, 256)
{
    extern __shared__ float sm[];
    float* qt = sm;                   // [32(d)][36(i)]  q transposed
    float* kt = sm + 32 * 36;         // pass1: [32(d)][68(j)] ; pass3: v [64(j)][36(d)]
    float* S  = sm + 32 * 36 + 64 * 36; // [32][SPAD]

    int tid = threadIdx.x;
    int i0 = blockIdx.x * 32;
    int h  = blockIdx.y;
    int b  = blockIdx.z;

    const float* qbase = qp + ((size_t)b * NQ + i0) * DIMC + h * DH;
    const float* kbase = kvp + (size_t)b * NK * (2 * DIMC) + h * DH;
    const float* vbase = kbase + DIMC;
    const float* bbase = bias + ((size_t)h * NQ + i0) * NK;

    // load q tile, transposed (d-major)
    {
        int i  = tid >> 3;
        int d4 = (tid & 7) << 2;
        float4 v = *(const float4*)(qbase + (size_t)i * DIMC + d4);
        qt[(d4 + 0) * 36 + i] = v.x;
        qt[(d4 + 1) * 36 + i] = v.y;
        qt[(d4 + 2) * 36 + i] = v.z;
        qt[(d4 + 3) * 36 + i] = v.w;
    }

    int ty  = tid >> 5;          // 0..7  -> q rows ty*4..+3
    int tx  = tid & 31;          // k cols tx*2..+1 within chunk
    int lj  = tid >> 3;          // loader row 0..31
    int ld4 = (tid & 7) << 2;    // loader d 0..28

    // -------- pass 1: scores --------
    #pragma unroll 1
    for (int kc = 0; kc < NK; kc += 64) {
        __syncthreads();   // q visible (1st iter) / prev compute done before kt overwrite
        #pragma unroll
        for (int jj = 0; jj < 2; ++jj) {
            int jr = lj + jj * 32;
            float4 v = *(const float4*)(kbase + (size_t)(kc + jr) * (2 * DIMC) + ld4);
            kt[(ld4 + 0) * 68 + jr] = v.x;
            kt[(ld4 + 1) * 68 + jr] = v.y;
            kt[(ld4 + 2) * 68 + jr] = v.z;
            kt[(ld4 + 3) * 68 + jr] = v.w;
        }
        __syncthreads();

        float a00 = 0, a01 = 0, a10 = 0, a11 = 0, a20 = 0, a21 = 0, a30 = 0, a31 = 0;
        #pragma unroll
        for (int d = 0; d < 32; ++d) {
            float4 a  = *(float4*)(qt + d * 36 + ty * 4);
            float2 bv = *(float2*)(kt + d * 68 + tx * 2);
            a00 += a.x * bv.x; a01 += a.x * bv.y;
            a10 += a.y * bv.x; a11 += a.y * bv.y;
            a20 += a.z * bv.x; a21 += a.z * bv.y;
            a30 += a.w * bv.x; a31 += a.w * bv.y;
        }
        int col = kc + tx * 2;
        float2 b0 = *(const float2*)(bbase + (size_t)(ty * 4 + 0) * NK + col);
        float2 b1 = *(const float2*)(bbase + (size_t)(ty * 4 + 1) * NK + col);
        float2 b2 = *(const float2*)(bbase + (size_t)(ty * 4 + 2) * NK + col);
        float2 b3 = *(const float2*)(bbase + (size_t)(ty * 4 + 3) * NK + col);
        S[(ty * 4 + 0) * SPAD + col]     = a00 + b0.x;
        S[(ty * 4 + 0) * SPAD + col + 1] = a01 + b0.y;
        S[(ty * 4 + 1) * SPAD + col]     = a10 + b1.x;
        S[(ty * 4 + 1) * SPAD + col + 1] = a11 + b1.y;
        S[(ty * 4 + 2) * SPAD + col]     = a20 + b2.x;
        S[(ty * 4 + 2) * SPAD + col + 1] = a21 + b2.y;
        S[(ty * 4 + 3) * SPAD + col]     = a30 + b3.x;
        S[(ty * 4 + 3) * SPAD + col + 1] = a31 + b3.y;
    }
    __syncthreads();

    // -------- pass 2: softmax (1 warp -> 4 rows) --------
    {
        int w = tid >> 5, lane = tid & 31;
        #pragma unroll 1
        for (int rr = 0; rr < 4; ++rr) {
            float* Sr = S + (w * 4 + rr) * SPAD;
            float vals[18];
            float m = -1e30f;
            #pragma unroll
            for (int c = 0; c < 18; ++c) {
                vals[c] = Sr[lane + c * 32];
                m = fmaxf(m, vals[c]);
            }
            #pragma unroll
            for (int off = 16; off; off >>= 1)
                m = fmaxf(m, __shfl_xor_sync(0xffffffffu, m, off));
            float ssum = 0.f;
            #pragma unroll
            for (int c = 0; c < 18; ++c) {
                vals[c] = __expf(vals[c] - m);
                ssum += vals[c];
            }
            #pragma unroll
            for (int off = 16; off; off >>= 1)
                ssum += __shfl_xor_sync(0xffffffffu, ssum, off);
            float inv = 1.0f / ssum;
            #pragma unroll
            for (int c = 0; c < 18; ++c)
                Sr[lane + c * 32] = vals[c] * inv;
        }
    }

    // -------- pass 3: O = P @ V --------
    {
        float* vsm = kt;            // reuse: [64(j)][36(d)]
        int i  = tid >> 3;          // out row 0..31
        int d4 = (tid & 7) << 2;    // out col group
        float ax = 0, ay = 0, az = 0, aw = 0;
        #pragma unroll 1
        for (int kc = 0; kc < NK; kc += 64) {
            __syncthreads();  // softmax done (1st iter) / prev compute done
            #pragma unroll
            for (int jj = 0; jj < 2; ++jj) {
                int jr = lj + jj * 32;
                *(float4*)(vsm + jr * 36 + ld4) =
                    *(const float4*)(vbase + (size_t)(kc + jr) * (2 * DIMC) + ld4);
            }
            __syncthreads();
            #pragma unroll 8
            for (int j = 0; j < 64; ++j) {
                float p  = S[i * SPAD + kc + j];
                float4 v = *(float4*)(vsm + j * 36 + d4);
                ax += p * v.x; ay += p * v.y; az += p * v.z; aw += p * v.w;
            }
        }
        float4 o; o.x = ax; o.y = ay; o.z = az; o.w = aw;
        *(float4*)(outp + ((size_t)b * NQ + i0 + i) * DIMC + h * DH + d4) = o;
    }
}

// ---------------- launcher ----------------
extern "C" void kernel_launch(void* const* d_in, const int* in_sizes, int n_in,
                              void* d_out, int out_size)
{
    (void)in_sizes; (void)n_in; (void)out_size;
    const float* q_w    = (const float*)d_in[0];
    const float* kv_w   = (const float*)d_in[1];
    const float* q_W    = (const float*)d_in[2];
    const float* q_b    = (const float*)d_in[3];
    const float* kv_W   = (const float*)d_in[4];
    const float* kv_b   = (const float*)d_in[5];
    const float* proj_W = (const float*)d_in[6];
    const float* proj_b = (const float*)d_in[7];
    const float* btab   = (const float*)d_in[8];
    const int*   ridx   = (const int*)d_in[9];
    float* out = (float*)d_out;

    float *gq, *gkv, *gb, *ga;
    cudaGetSymbolAddress((void**)&gq,  g_q);
    cudaGetSymbolAddress((void**)&gkv, g_kv);
    cudaGetSymbolAddress((void**)&gb,  g_bias);
    cudaGetSymbolAddress((void**)&ga,  g_att);

    cudaFuncSetAttribute(attn_kernel,
                         cudaFuncAttributeMaxDynamicSharedMemorySize, ATT_SMEM);

    // 1) relative-position bias gather -> (H, Nq, Nk)
    bias_gather_kernel<<<(NQ * NK) / 256, 256>>>(btab, ridx, gb);

    // 2) kv projection: (B*Nk,256) @ (256,512) + b   [tf32 tensor cores]
    tf32_gemm_bias_kernel<<<dim3(512 / 128, (NB * NK) / 128), 256>>>(
        kv_w, kv_W, kv_b, gkv, 512, 1.0f);

    // 3) q projection (pre-scaled by Dh^-0.5): (B*Nq,256) @ (256,256) + b
    tf32_gemm_bias_kernel<<<dim3(256 / 128, (NB * NQ) / 128), 256>>>(
        q_w, q_W, q_b, gq, 256, 0.17677669529663687f);

    // 4) fused attention
    attn_kernel<<<dim3(NQ / 32, HEADS, NB), 256, ATT_SMEM>>>(gq, gkv, gb, ga);

    // 5) output projection: (B*Nq,256) @ (256,256) + b
    tf32_gemm_bias_kernel<<<dim3(256 / 128, (NB * NQ) / 128), 256>>>(
        ga, proj_W, proj_b, out, 256, 1.0f);
}

// round 11
// speedup vs baseline: 2.0194x; 1.5711x over previous
#include <cuda_runtime.h>
#include <math.h>

#define NB    256   // batch*windows
#define DIMC  256
#define HEADS 8
#define DH    32
#define NQ    256
#define NK    576

// ---------------- scratch (static __device__: no allocation) ----------------
__device__ float g_q[16777216];     // (B*Nq, 256)  q-proj, pre-scaled
__device__ float g_kv[75497472];    // (B*Nk, 512)  [k | v] per token
__device__ float g_bias[1179648];   // (H, Nq, Nk)  gathered rel-pos bias
__device__ float g_att[16777216];   // (B*Nq, 256)  attention output

// ---------------- bias gather ----------------
__global__ __launch_bounds__(256) void bias_gather_kernel(
    const float* __restrict__ table, const int* __restrict__ rel,
    float* __restrict__ out)
{
    int idx = blockIdx.x * 256 + threadIdx.x;      // < Nq*Nk = 147456
    int r = rel[idx];
    const float* t = table + r * HEADS;
    #pragma unroll
    for (int h = 0; h < HEADS; ++h)
        out[h * (NQ * NK) + idx] = t[h];
}

// ---------------- tf32 helpers ----------------
__device__ __forceinline__ unsigned f2tf(float f)
{
    unsigned u;
    asm("cvt.rna.tf32.f32 %0, %1;" : "=r"(u) : "f"(f));
    return u;
}

__device__ __forceinline__ void mma_tf32(float c[4],
                                         const unsigned a[4],
                                         const unsigned b[2])
{
    asm volatile(
        "mma.sync.aligned.m16n8k8.row.col.f32.tf32.tf32.f32 "
        "{%0,%1,%2,%3}, {%4,%5,%6,%7}, {%8,%9}, {%0,%1,%2,%3};\n"
        : "+f"(c[0]), "+f"(c[1]), "+f"(c[2]), "+f"(c[3])
        : "r"(a[0]), "r"(a[1]), "r"(a[2]), "r"(a[3]),
          "r"(b[0]), "r"(b[1]));
}

// ------- tf32 tensor-core GEMM: C = (A @ W + bias) * scale, K fixed = 256 ---
#define ASTRIDE 20
#define BSTRIDE 136

__global__ __launch_bounds__(256) void tf32_gemm_bias_kernel(
    const float* __restrict__ A, const float* __restrict__ W,
    const float* __restrict__ bias, float* __restrict__ C,
    int N, float scale)
{
    const int K = 256;
    __shared__ unsigned As[2][128 * ASTRIDE];
    __shared__ unsigned Bs[2][16 * BSTRIDE];

    int tid  = threadIdx.x;
    int lane = tid & 31, warp = tid >> 5;
    int wm = warp & 1, wn = warp >> 1;
    int grp = lane >> 2, qid = lane & 3;

    const float* Ab = A + (size_t)blockIdx.y * 128 * K;
    const float* Wb = W + blockIdx.x * 128;

    int ar  = tid >> 2;
    int aq  = tid & 3;
    int bk  = tid >> 5;
    int bc4 = (tid & 31) << 2;

    float acc[4][4][4];
    #pragma unroll
    for (int i = 0; i < 4; ++i)
        #pragma unroll
        for (int j = 0; j < 4; ++j)
            #pragma unroll
            for (int r = 0; r < 4; ++r) acc[i][j][r] = 0.f;

    float4 ra0 = *(const float4*)(Ab + (size_t)ar * K + aq * 4);
    float4 ra1 = *(const float4*)(Ab + (size_t)(ar + 64) * K + aq * 4);
    float4 rb0 = *(const float4*)(Wb + (size_t)bk * N + bc4);
    float4 rb1 = *(const float4*)(Wb + (size_t)(bk + 8) * N + bc4);

    {
        uint4 u;
        u = make_uint4(f2tf(ra0.x), f2tf(ra0.y), f2tf(ra0.z), f2tf(ra0.w));
        *(uint4*)&As[0][ar * ASTRIDE + aq * 4] = u;
        u = make_uint4(f2tf(ra1.x), f2tf(ra1.y), f2tf(ra1.z), f2tf(ra1.w));
        *(uint4*)&As[0][(ar + 64) * ASTRIDE + aq * 4] = u;
        u = make_uint4(f2tf(rb0.x), f2tf(rb0.y), f2tf(rb0.z), f2tf(rb0.w));
        *(uint4*)&Bs[0][bk * BSTRIDE + bc4] = u;
        u = make_uint4(f2tf(rb1.x), f2tf(rb1.y), f2tf(rb1.z), f2tf(rb1.w));
        *(uint4*)&Bs[0][(bk + 8) * BSTRIDE + bc4] = u;
    }
    __syncthreads();

    int s = 0;
    #pragma unroll 1
    for (int kc = 0; kc < K / 16; ++kc) {
        if (kc + 1 < K / 16) {
            int k0 = (kc + 1) * 16;
            ra0 = *(const float4*)(Ab + (size_t)ar * K + k0 + aq * 4);
            ra1 = *(const float4*)(Ab + (size_t)(ar + 64) * K + k0 + aq * 4);
            rb0 = *(const float4*)(Wb + (size_t)(k0 + bk) * N + bc4);
            rb1 = *(const float4*)(Wb + (size_t)(k0 + bk + 8) * N + bc4);
        }

        const unsigned* Ap = &As[s][0];
        const unsigned* Bp = &Bs[s][0];
        #pragma unroll
        for (int ks = 0; ks < 2; ++ks) {
            unsigned af[4][4], bf[4][2];
            #pragma unroll
            for (int mf = 0; mf < 4; ++mf) {
                int r0 = (wm * 64 + mf * 16 + grp) * ASTRIDE + ks * 8 + qid;
                af[mf][0] = Ap[r0];
                af[mf][1] = Ap[r0 + 8 * ASTRIDE];
                af[mf][2] = Ap[r0 + 4];
                af[mf][3] = Ap[r0 + 8 * ASTRIDE + 4];
            }
            #pragma unroll
            for (int nf = 0; nf < 4; ++nf) {
                int c0 = (ks * 8 + qid) * BSTRIDE + wn * 32 + nf * 8 + grp;
                bf[nf][0] = Bp[c0];
                bf[nf][1] = Bp[c0 + 4 * BSTRIDE];
            }
            #pragma unroll
            for (int mf = 0; mf < 4; ++mf)
                #pragma unroll
                for (int nf = 0; nf < 4; ++nf)
                    mma_tf32(acc[mf][nf], af[mf], bf[nf]);
        }

        if (kc + 1 < K / 16) {
            int ns = s ^ 1;
            uint4 u;
            u = make_uint4(f2tf(ra0.x), f2tf(ra0.y), f2tf(ra0.z), f2tf(ra0.w));
            *(uint4*)&As[ns][ar * ASTRIDE + aq * 4] = u;
            u = make_uint4(f2tf(ra1.x), f2tf(ra1.y), f2tf(ra1.z), f2tf(ra1.w));
            *(uint4*)&As[ns][(ar + 64) * ASTRIDE + aq * 4] = u;
            u = make_uint4(f2tf(rb0.x), f2tf(rb0.y), f2tf(rb0.z), f2tf(rb0.w));
            *(uint4*)&Bs[ns][bk * BSTRIDE + bc4] = u;
            u = make_uint4(f2tf(rb1.x), f2tf(rb1.y), f2tf(rb1.z), f2tf(rb1.w));
            *(uint4*)&Bs[ns][(bk + 8) * BSTRIDE + bc4] = u;
            __syncthreads();
            s = ns;
        }
    }

    int row0 = blockIdx.y * 128 + wm * 64;
    int col0 = blockIdx.x * 128 + wn * 32;
    #pragma unroll
    for (int mf = 0; mf < 4; ++mf) {
        int r = row0 + mf * 16 + grp;
        #pragma unroll
        for (int nf = 0; nf < 4; ++nf) {
            int c = col0 + nf * 8 + qid * 2;
            float bx = __ldg(bias + c);
            float by = __ldg(bias + c + 1);
            float2 o0, o1;
            o0.x = (acc[mf][nf][0] + bx) * scale;
            o0.y = (acc[mf][nf][1] + by) * scale;
            o1.x = (acc[mf][nf][2] + bx) * scale;
            o1.y = (acc[mf][nf][3] + by) * scale;
            *(float2*)(C + (size_t)r * N + c)       = o0;
            *(float2*)(C + (size_t)(r + 8) * N + c) = o1;
        }
    }
}

// ------- fused attention (tensor-core): S = QK^T + bias; softmax; O = P V ---
// Per CTA: (b, h, 32 q rows). 256 threads = 8 warps.
//   Qs: tf32 [32 rows][36]          (bank = 4*row+qid: conflict-free frags)
//   Ks: tf32 [64 tok][36]  (pass1)  / Vt: tf32 [32 d][68] (pass3), shared buf
//   S : fp32 [32][588]              (bank = 12*row+qid: conflict-free frags)
#define SPAD 588
#define QS_W (32 * 36)
#define KS_W (64 * 36)
#define ATT_SMEM ((QS_W + KS_W + 32 * SPAD) * 4)

__global__ __launch_bounds__(256) void attn_kernel(
    const float* __restrict__ qp,    // (B*Nq, 256), already *scale
    const float* __restrict__ kvp,   // (B*Nk, 512)
    const float* __restrict__ bias,  // (H, Nq, Nk)
    float* __restrict__ outp)        // (B*Nq, 256)
{
    extern __shared__ float sm[];
    unsigned* qs = (unsigned*)sm;            // [32][36]
    unsigned* kb = (unsigned*)(sm + QS_W);   // K chunk [64][36] / Vt [32][68]
    float*    S  = sm + QS_W + KS_W;         // [32][SPAD]
    const unsigned* Su = (const unsigned*)S;

    int tid  = threadIdx.x;
    int lane = tid & 31, warp = tid >> 5;
    int grp = lane >> 2, qid = lane & 3;

    int i0 = blockIdx.x * 32;
    int h  = blockIdx.y;
    int b  = blockIdx.z;

    const float* qbase = qp + ((size_t)b * NQ + i0) * DIMC + h * DH;
    const float* kbase = kvp + (size_t)b * NK * (2 * DIMC) + h * DH;
    const float* vbase = kbase + DIMC;
    const float* bbase = bias + ((size_t)h * NQ + i0) * NK;

    // stage Q as tf32, row-major [row][36]
    {
        int r  = tid >> 3;
        int d4 = (tid & 7) << 2;
        float4 v = *(const float4*)(qbase + (size_t)r * DIMC + d4);
        unsigned* dst = qs + r * 36 + d4;
        dst[0] = f2tf(v.x); dst[1] = f2tf(v.y);
        dst[2] = f2tf(v.z); dst[3] = f2tf(v.w);
    }

    // -------- pass 1: S = Q @ K^T + bias --------
    #pragma unroll 1
    for (int kc = 0; kc < NK; kc += 64) {
        __syncthreads();   // q staged (1st) / prev frag loads done
        {   // K chunk: [token][d], natural layout == col-major B operand
            int t  = tid >> 2;
            int d8 = (tid & 3) << 3;
            const float* src = kbase + (size_t)(kc + t) * (2 * DIMC) + d8;
            float4 v0 = *(const float4*)src;
            float4 v1 = *(const float4*)(src + 4);
            unsigned* dst = kb + t * 36 + d8;
            dst[0] = f2tf(v0.x); dst[1] = f2tf(v0.y);
            dst[2] = f2tf(v0.z); dst[3] = f2tf(v0.w);
            dst[4] = f2tf(v1.x); dst[5] = f2tf(v1.y);
            dst[6] = f2tf(v1.z); dst[7] = f2tf(v1.w);
        }
        __syncthreads();

        float c0[4] = {0.f, 0.f, 0.f, 0.f};
        float c1[4] = {0.f, 0.f, 0.f, 0.f};
        #pragma unroll
        for (int ks = 0; ks < 4; ++ks) {
            unsigned af0[4], af1[4], bf[2];
            int a0 = grp * 36 + ks * 8 + qid;
            af0[0] = qs[a0];
            af0[1] = qs[a0 + 8 * 36];
            af0[2] = qs[a0 + 4];
            af0[3] = qs[a0 + 8 * 36 + 4];
            af1[0] = qs[a0 + 16 * 36];
            af1[1] = qs[a0 + 24 * 36];
            af1[2] = qs[a0 + 16 * 36 + 4];
            af1[3] = qs[a0 + 24 * 36 + 4];
            int bi = (warp * 8 + grp) * 36 + ks * 8 + qid;
            bf[0] = kb[bi];
            bf[1] = kb[bi + 4];
            mma_tf32(c0, af0, bf);
            mma_tf32(c1, af1, bf);
        }
        int col = kc + warp * 8 + qid * 2;
        {
            float2 b0 = *(const float2*)(bbase + (size_t)(grp)      * NK + col);
            float2 b1 = *(const float2*)(bbase + (size_t)(grp + 8)  * NK + col);
            float2 b2 = *(const float2*)(bbase + (size_t)(grp + 16) * NK + col);
            float2 b3 = *(const float2*)(bbase + (size_t)(grp + 24) * NK + col);
            S[(grp)      * SPAD + col]     = c0[0] + b0.x;
            S[(grp)      * SPAD + col + 1] = c0[1] + b0.y;
            S[(grp + 8)  * SPAD + col]     = c0[2] + b1.x;
            S[(grp + 8)  * SPAD + col + 1] = c0[3] + b1.y;
            S[(grp + 16) * SPAD + col]     = c1[0] + b2.x;
            S[(grp + 16) * SPAD + col + 1] = c1[1] + b2.y;
            S[(grp + 24) * SPAD + col]     = c1[2] + b3.x;
            S[(grp + 24) * SPAD + col + 1] = c1[3] + b3.y;
        }
    }
    __syncthreads();

    // -------- pass 2: softmax (1 warp -> 4 rows); write P rounded to tf32 ---
    {
        #pragma unroll 1
        for (int rr = 0; rr < 4; ++rr) {
            float* Sr = S + (warp * 4 + rr) * SPAD;
            float vals[18];
            float m = -1e30f;
            #pragma unroll
            for (int c = 0; c < 18; ++c) {
                vals[c] = Sr[lane + c * 32];
                m = fmaxf(m, vals[c]);
            }
            #pragma unroll
            for (int off = 16; off; off >>= 1)
                m = fmaxf(m, __shfl_xor_sync(0xffffffffu, m, off));
            float ssum = 0.f;
            #pragma unroll
            for (int c = 0; c < 18; ++c) {
                vals[c] = __expf(vals[c] - m);
                ssum += vals[c];
            }
            #pragma unroll
            for (int off = 16; off; off >>= 1)
                ssum += __shfl_xor_sync(0xffffffffu, ssum, off);
            float inv = 1.0f / ssum;
            #pragma unroll
            for (int c = 0; c < 18; ++c)
                Sr[lane + c * 32] = __uint_as_float(f2tf(vals[c] * inv));
        }
    }

    // -------- pass 3: O = P @ V --------
    {
        int mf = warp & 1;          // 16-row slab
        int nf = warp >> 1;         // 8-d slab
        float acc[4] = {0.f, 0.f, 0.f, 0.f};
        int lj  = tid >> 3;
        int ld4 = (tid & 7) << 2;

        #pragma unroll 1
        for (int kc = 0; kc < NK; kc += 64) {
            __syncthreads();   // softmax done (1st) / prev frag loads done
            #pragma unroll
            for (int jj = 0; jj < 2; ++jj) {   // Vt: [d][68], transposed store
                int tok = lj + jj * 32;
                float4 v = *(const float4*)(vbase + (size_t)(kc + tok) * (2 * DIMC) + ld4);
                kb[(ld4 + 0) * 68 + tok] = f2tf(v.x);
                kb[(ld4 + 1) * 68 + tok] = f2tf(v.y);
                kb[(ld4 + 2) * 68 + tok] = f2tf(v.z);
                kb[(ld4 + 3) * 68 + tok] = f2tf(v.w);
            }
            __syncthreads();

            #pragma unroll
            for (int ks = 0; ks < 8; ++ks) {
                unsigned af[4], bf[2];
                int a0 = (mf * 16 + grp) * SPAD + kc + ks * 8 + qid;
                af[0] = Su[a0];
                af[1] = Su[a0 + 8 * SPAD];
                af[2] = Su[a0 + 4];
                af[3] = Su[a0 + 8 * SPAD + 4];
                int bi = (nf * 8 + grp) * 68 + ks * 8 + qid;
                bf[0] = kb[bi];
                bf[1] = kb[bi + 4];
                mma_tf32(acc, af, bf);
            }
        }

        int r = mf * 16 + grp;
        int c = nf * 8 + qid * 2;
        float* o = outp + ((size_t)b * NQ + i0 + r) * DIMC + h * DH + c;
        float2 o0, o1;
        o0.x = acc[0]; o0.y = acc[1];
        o1.x = acc[2]; o1.y = acc[3];
        *(float2*)o              = o0;
        *(float2*)(o + 8 * DIMC) = o1;
    }
}

// ---------------- launcher ----------------
extern "C" void kernel_launch(void* const* d_in, const int* in_sizes, int n_in,
                              void* d_out, int out_size)
{
    (void)in_sizes; (void)n_in; (void)out_size;
    const float* q_w    = (const float*)d_in[0];
    const float* kv_w   = (const float*)d_in[1];
    const float* q_W    = (const float*)d_in[2];
    const float* q_b    = (const float*)d_in[3];
    const float* kv_W   = (const float*)d_in[4];
    const float* kv_b   = (const float*)d_in[5];
    const float* proj_W = (const float*)d_in[6];
    const float* proj_b = (const float*)d_in[7];
    const float* btab   = (const float*)d_in[8];
    const int*   ridx   = (const int*)d_in[9];
    float* out = (float*)d_out;

    float *gq, *gkv, *gb, *ga;
    cudaGetSymbolAddress((void**)&gq,  g_q);
    cudaGetSymbolAddress((void**)&gkv, g_kv);
    cudaGetSymbolAddress((void**)&gb,  g_bias);
    cudaGetSymbolAddress((void**)&ga,  g_att);

    cudaFuncSetAttribute(attn_kernel,
                         cudaFuncAttributeMaxDynamicSharedMemorySize, ATT_SMEM);

    // 1) relative-position bias gather -> (H, Nq, Nk)
    bias_gather_kernel<<<(NQ * NK) / 256, 256>>>(btab, ridx, gb);

    // 2) kv projection: (B*Nk,256) @ (256,512) + b   [tf32 tensor cores]
    tf32_gemm_bias_kernel<<<dim3(512 / 128, (NB * NK) / 128), 256>>>(
        kv_w, kv_W, kv_b, gkv, 512, 1.0f);

    // 3) q projection (pre-scaled by Dh^-0.5): (B*Nq,256) @ (256,256) + b
    tf32_gemm_bias_kernel<<<dim3(256 / 128, (NB * NQ) / 128), 256>>>(
        q_w, q_W, q_b, gq, 256, 0.17677669529663687f);

    // 4) fused attention (tensor cores)
    attn_kernel<<<dim3(NQ / 32, HEADS, NB), 256, ATT_SMEM>>>(gq, gkv, gb, ga);

    // 5) output projection: (B*Nq,256) @ (256,256) + b
    tf32_gemm_bias_kernel<<<dim3(256 / 128, (NB * NQ) / 128), 256>>>(
        ga, proj_W, proj_b, out, 256, 1.0f);
}

// round 12
// speedup vs baseline: 3.7285x; 1.8463x over previous
#include <cuda_runtime.h>
#include <math.h>

#define NB    256   // batch*windows
#define DIMC  256
#define HEADS 8
#define DH    32
#define NQ    256
#define NK    576

// ---------------- scratch (static __device__: no allocation) ----------------
__device__ float g_q[16777216];     // (B*Nq, 256)  q-proj, pre-scaled
__device__ float g_kv[75497472];    // (B*Nk, 512)  [k | v] per token
__device__ float g_bias[1179648];   // (H, Nq, Nk)  gathered rel-pos bias
__device__ float g_att[16777216];   // (B*Nq, 256)  attention output

// ---------------- bias gather ----------------
__global__ __launch_bounds__(256) void bias_gather_kernel(
    const float* __restrict__ table, const int* __restrict__ rel,
    float* __restrict__ out)
{
    int idx = blockIdx.x * 256 + threadIdx.x;      // < Nq*Nk = 147456
    int r = rel[idx];
    const float* t = table + r * HEADS;
    #pragma unroll
    for (int h = 0; h < HEADS; ++h)
        out[h * (NQ * NK) + idx] = t[h];
}

// ---------------- tf32 helpers ----------------
__device__ __forceinline__ unsigned f2tf(float f)
{
    unsigned u;
    asm("cvt.rna.tf32.f32 %0, %1;" : "=r"(u) : "f"(f));
    return u;
}

__device__ __forceinline__ void mma_tf32(float c[4],
                                         const unsigned a[4],
                                         const unsigned b[2])
{
    asm volatile(
        "mma.sync.aligned.m16n8k8.row.col.f32.tf32.tf32.f32 "
        "{%0,%1,%2,%3}, {%4,%5,%6,%7}, {%8,%9}, {%0,%1,%2,%3};\n"
        : "+f"(c[0]), "+f"(c[1]), "+f"(c[2]), "+f"(c[3])
        : "r"(a[0]), "r"(a[1]), "r"(a[2]), "r"(a[3]),
          "r"(b[0]), "r"(b[1]));
}

// ------- tf32 tensor-core GEMM: C = (A @ W + bias) * scale, K fixed = 256 ---
#define ASTRIDE 20
#define BSTRIDE 136

__global__ __launch_bounds__(256) void tf32_gemm_bias_kernel(
    const float* __restrict__ A, const float* __restrict__ W,
    const float* __restrict__ bias, float* __restrict__ C,
    int N, float scale)
{
    const int K = 256;
    __shared__ unsigned As[2][128 * ASTRIDE];
    __shared__ unsigned Bs[2][16 * BSTRIDE];

    int tid  = threadIdx.x;
    int lane = tid & 31, warp = tid >> 5;
    int wm = warp & 1, wn = warp >> 1;
    int grp = lane >> 2, qid = lane & 3;

    const float* Ab = A + (size_t)blockIdx.y * 128 * K;
    const float* Wb = W + blockIdx.x * 128;

    int ar  = tid >> 2;
    int aq  = tid & 3;
    int bk  = tid >> 5;
    int bc4 = (tid & 31) << 2;

    float acc[4][4][4];
    #pragma unroll
    for (int i = 0; i < 4; ++i)
        #pragma unroll
        for (int j = 0; j < 4; ++j)
            #pragma unroll
            for (int r = 0; r < 4; ++r) acc[i][j][r] = 0.f;

    float4 ra0 = *(const float4*)(Ab + (size_t)ar * K + aq * 4);
    float4 ra1 = *(const float4*)(Ab + (size_t)(ar + 64) * K + aq * 4);
    float4 rb0 = *(const float4*)(Wb + (size_t)bk * N + bc4);
    float4 rb1 = *(const float4*)(Wb + (size_t)(bk + 8) * N + bc4);

    {
        uint4 u;
        u = make_uint4(f2tf(ra0.x), f2tf(ra0.y), f2tf(ra0.z), f2tf(ra0.w));
        *(uint4*)&As[0][ar * ASTRIDE + aq * 4] = u;
        u = make_uint4(f2tf(ra1.x), f2tf(ra1.y), f2tf(ra1.z), f2tf(ra1.w));
        *(uint4*)&As[0][(ar + 64) * ASTRIDE + aq * 4] = u;
        u = make_uint4(f2tf(rb0.x), f2tf(rb0.y), f2tf(rb0.z), f2tf(rb0.w));
        *(uint4*)&Bs[0][bk * BSTRIDE + bc4] = u;
        u = make_uint4(f2tf(rb1.x), f2tf(rb1.y), f2tf(rb1.z), f2tf(rb1.w));
        *(uint4*)&Bs[0][(bk + 8) * BSTRIDE + bc4] = u;
    }
    __syncthreads();

    int s = 0;
    #pragma unroll 1
    for (int kc = 0; kc < K / 16; ++kc) {
        if (kc + 1 < K / 16) {
            int k0 = (kc + 1) * 16;
            ra0 = *(const float4*)(Ab + (size_t)ar * K + k0 + aq * 4);
            ra1 = *(const float4*)(Ab + (size_t)(ar + 64) * K + k0 + aq * 4);
            rb0 = *(const float4*)(Wb + (size_t)(k0 + bk) * N + bc4);
            rb1 = *(const float4*)(Wb + (size_t)(k0 + bk + 8) * N + bc4);
        }

        const unsigned* Ap = &As[s][0];
        const unsigned* Bp = &Bs[s][0];
        #pragma unroll
        for (int ks = 0; ks < 2; ++ks) {
            unsigned af[4][4], bf[4][2];
            #pragma unroll
            for (int mf = 0; mf < 4; ++mf) {
                int r0 = (wm * 64 + mf * 16 + grp) * ASTRIDE + ks * 8 + qid;
                af[mf][0] = Ap[r0];
                af[mf][1] = Ap[r0 + 8 * ASTRIDE];
                af[mf][2] = Ap[r0 + 4];
                af[mf][3] = Ap[r0 + 8 * ASTRIDE + 4];
            }
            #pragma unroll
            for (int nf = 0; nf < 4; ++nf) {
                int c0 = (ks * 8 + qid) * BSTRIDE + wn * 32 + nf * 8 + grp;
                bf[nf][0] = Bp[c0];
                bf[nf][1] = Bp[c0 + 4 * BSTRIDE];
            }
            #pragma unroll
            for (int mf = 0; mf < 4; ++mf)
                #pragma unroll
                for (int nf = 0; nf < 4; ++nf)
                    mma_tf32(acc[mf][nf], af[mf], bf[nf]);
        }

        if (kc + 1 < K / 16) {
            int ns = s ^ 1;
            uint4 u;
            u = make_uint4(f2tf(ra0.x), f2tf(ra0.y), f2tf(ra0.z), f2tf(ra0.w));
            *(uint4*)&As[ns][ar * ASTRIDE + aq * 4] = u;
            u = make_uint4(f2tf(ra1.x), f2tf(ra1.y), f2tf(ra1.z), f2tf(ra1.w));
            *(uint4*)&As[ns][(ar + 64) * ASTRIDE + aq * 4] = u;
            u = make_uint4(f2tf(rb0.x), f2tf(rb0.y), f2tf(rb0.z), f2tf(rb0.w));
            *(uint4*)&Bs[ns][bk * BSTRIDE + bc4] = u;
            u = make_uint4(f2tf(rb1.x), f2tf(rb1.y), f2tf(rb1.z), f2tf(rb1.w));
            *(uint4*)&Bs[ns][(bk + 8) * BSTRIDE + bc4] = u;
            __syncthreads();
            s = ns;
        }
    }

    int row0 = blockIdx.y * 128 + wm * 64;
    int col0 = blockIdx.x * 128 + wn * 32;
    #pragma unroll
    for (int mf = 0; mf < 4; ++mf) {
        int r = row0 + mf * 16 + grp;
        #pragma unroll
        for (int nf = 0; nf < 4; ++nf) {
            int c = col0 + nf * 8 + qid * 2;
            float bx = __ldg(bias + c);
            float by = __ldg(bias + c + 1);
            float2 o0, o1;
            o0.x = (acc[mf][nf][0] + bx) * scale;
            o0.y = (acc[mf][nf][1] + by) * scale;
            o1.x = (acc[mf][nf][2] + bx) * scale;
            o1.y = (acc[mf][nf][3] + by) * scale;
            *(float2*)(C + (size_t)r * N + c)       = o0;
            *(float2*)(C + (size_t)(r + 8) * N + c) = o1;
        }
    }
}

// ---- flash attention (tensor-core, online softmax, S in registers) ---------
// CTA = (qtile of 128 rows, h, b). 8 warps x 16 q-rows. K chunks of 64 tokens.
//   Qs : tf32 [128][36]  (loaded once, fragments cached in registers)
//   K  : tf32 [2][64 tok][36]   (vectorized stores: conflict-free)
//   Vt : tf32 [2][32 d][68]     (transposed; frag loads conflict-free)
#define QSW (128 * 36)
#define KCW (64 * 36)
#define VCW (32 * 68)
#define ATT_SMEM ((QSW + 2 * KCW + 2 * VCW) * 4)

__global__ __launch_bounds__(256) void attn_kernel(
    const float* __restrict__ qp,    // (B*Nq, 256), already *scale
    const float* __restrict__ kvp,   // (B*Nk, 512)
    const float* __restrict__ bias,  // (H, Nq, Nk)
    float* __restrict__ outp)        // (B*Nq, 256)
{
    extern __shared__ float smf[];
    unsigned* qs   = (unsigned*)smf;             // [128][36]
    unsigned* kbuf = (unsigned*)smf + QSW;       // [2][64*36]
    unsigned* vbuf = (unsigned*)smf + QSW + 2 * KCW; // [2][32*68]

    int tid  = threadIdx.x;
    int lane = tid & 31, warp = tid >> 5;
    int grp = lane >> 2, qid = lane & 3;

    int i0 = blockIdx.x * 128;
    int h  = blockIdx.y;
    int b  = blockIdx.z;

    const float* qbase = qp + ((size_t)b * NQ + i0) * DIMC + h * DH;
    const float* kbase = kvp + (size_t)b * NK * (2 * DIMC) + h * DH;
    const float* vbase = kbase + DIMC;
    const float* bb = bias + ((size_t)h * NQ + i0 + warp * 16) * NK;

    // ---- stage Q (tf32, [row][36]) ----
    {
        int r  = tid >> 1;
        int c0 = (tid & 1) * 16;
        const float* src = qbase + (size_t)r * DIMC + c0;
        unsigned* dst = qs + r * 36 + c0;
        #pragma unroll
        for (int i = 0; i < 4; ++i) {
            float4 v = *(const float4*)(src + i * 4);
            *(uint4*)(dst + i * 4) =
                make_uint4(f2tf(v.x), f2tf(v.y), f2tf(v.z), f2tf(v.w));
        }
    }

    // loader indices
    int ktok = tid >> 2, kd8 = (tid & 3) << 3;
    int vtok = tid >> 3, vd4 = (tid & 7) << 2;

    // ---- prefetch + store chunk 0 ----
    float4 kr0 = *(const float4*)(kbase + (size_t)ktok * (2 * DIMC) + kd8);
    float4 kr1 = *(const float4*)(kbase + (size_t)ktok * (2 * DIMC) + kd8 + 4);
    float4 vr0 = *(const float4*)(vbase + (size_t)vtok * (2 * DIMC) + vd4);
    float4 vr1 = *(const float4*)(vbase + (size_t)(vtok + 32) * (2 * DIMC) + vd4);
    {
        unsigned* kb = kbuf;
        *(uint4*)(kb + ktok * 36 + kd8) =
            make_uint4(f2tf(kr0.x), f2tf(kr0.y), f2tf(kr0.z), f2tf(kr0.w));
        *(uint4*)(kb + ktok * 36 + kd8 + 4) =
            make_uint4(f2tf(kr1.x), f2tf(kr1.y), f2tf(kr1.z), f2tf(kr1.w));
        unsigned* vb = vbuf;
        vb[(vd4 + 0) * 68 + vtok] = f2tf(vr0.x);
        vb[(vd4 + 1) * 68 + vtok] = f2tf(vr0.y);
        vb[(vd4 + 2) * 68 + vtok] = f2tf(vr0.z);
        vb[(vd4 + 3) * 68 + vtok] = f2tf(vr0.w);
        vb[(vd4 + 0) * 68 + vtok + 32] = f2tf(vr1.x);
        vb[(vd4 + 1) * 68 + vtok + 32] = f2tf(vr1.y);
        vb[(vd4 + 2) * 68 + vtok + 32] = f2tf(vr1.z);
        vb[(vd4 + 3) * 68 + vtok + 32] = f2tf(vr1.w);
    }
    __syncthreads();

    // ---- Q fragments: once, kept in registers ----
    unsigned qa[4][4];
    #pragma unroll
    for (int ks = 0; ks < 4; ++ks) {
        int a0 = (warp * 16 + grp) * 36 + ks * 8 + qid;
        qa[ks][0] = qs[a0];
        qa[ks][1] = qs[a0 + 8 * 36];
        qa[ks][2] = qs[a0 + 4];
        qa[ks][3] = qs[a0 + 8 * 36 + 4];
    }

    float o[4][4];
    #pragma unroll
    for (int i = 0; i < 4; ++i)
        #pragma unroll
        for (int j = 0; j < 4; ++j) o[i][j] = 0.f;
    float M0 = -1e30f, M1 = -1e30f, l0 = 0.f, l1 = 0.f;

    int sbase = lane & 28;           // grp*4, for shuffles
    int s1 = sbase + (qid >> 1);
    int s2 = s1 + 2;
    bool esel = (qid & 1);

    #pragma unroll 1
    for (int kc = 0; kc < 9; ++kc) {
        int s = kc & 1;

        // prefetch next chunk (gmem -> regs)
        if (kc < 8) {
            const float* kn = kbase + (size_t)((kc + 1) * 64) * (2 * DIMC);
            const float* vn = vbase + (size_t)((kc + 1) * 64) * (2 * DIMC);
            kr0 = *(const float4*)(kn + (size_t)ktok * (2 * DIMC) + kd8);
            kr1 = *(const float4*)(kn + (size_t)ktok * (2 * DIMC) + kd8 + 4);
            vr0 = *(const float4*)(vn + (size_t)vtok * (2 * DIMC) + vd4);
            vr1 = *(const float4*)(vn + (size_t)(vtok + 32) * (2 * DIMC) + vd4);
        }

        // ---- QK^T: S chunk in registers ----
        float c[8][4];
        #pragma unroll
        for (int nf = 0; nf < 8; ++nf)
            #pragma unroll
            for (int j = 0; j < 4; ++j) c[nf][j] = 0.f;
        {
            const unsigned* kb = kbuf + s * KCW;
            #pragma unroll
            for (int nf = 0; nf < 8; ++nf) {
                #pragma unroll
                for (int ks = 0; ks < 4; ++ks) {
                    unsigned bf[2];
                    int bi = (nf * 8 + grp) * 36 + ks * 8 + qid;
                    bf[0] = kb[bi];
                    bf[1] = kb[bi + 4];
                    mma_tf32(c[nf], qa[ks], bf);
                }
            }
        }

        // ---- add bias ----
        {
            const float* br0 = bb + (size_t)grp * NK + kc * 64 + qid * 2;
            const float* br1 = bb + (size_t)(grp + 8) * NK + kc * 64 + qid * 2;
            #pragma unroll
            for (int nf = 0; nf < 8; ++nf) {
                float2 bA = *(const float2*)(br0 + nf * 8);
                float2 bB = *(const float2*)(br1 + nf * 8);
                c[nf][0] += bA.x; c[nf][1] += bA.y;
                c[nf][2] += bB.x; c[nf][3] += bB.y;
            }
        }

        // ---- store next chunk to the other buffer ----
        if (kc < 8) {
            unsigned* kb = kbuf + (s ^ 1) * KCW;
            *(uint4*)(kb + ktok * 36 + kd8) =
                make_uint4(f2tf(kr0.x), f2tf(kr0.y), f2tf(kr0.z), f2tf(kr0.w));
            *(uint4*)(kb + ktok * 36 + kd8 + 4) =
                make_uint4(f2tf(kr1.x), f2tf(kr1.y), f2tf(kr1.z), f2tf(kr1.w));
            unsigned* vb = vbuf + (s ^ 1) * VCW;
            vb[(vd4 + 0) * 68 + vtok] = f2tf(vr0.x);
            vb[(vd4 + 1) * 68 + vtok] = f2tf(vr0.y);
            vb[(vd4 + 2) * 68 + vtok] = f2tf(vr0.z);
            vb[(vd4 + 3) * 68 + vtok] = f2tf(vr0.w);
            vb[(vd4 + 0) * 68 + vtok + 32] = f2tf(vr1.x);
            vb[(vd4 + 1) * 68 + vtok + 32] = f2tf(vr1.y);
            vb[(vd4 + 2) * 68 + vtok + 32] = f2tf(vr1.z);
            vb[(vd4 + 3) * 68 + vtok + 32] = f2tf(vr1.w);
        }

        // ---- online softmax update ----
        {
            float mc0 = -1e30f, mc1 = -1e30f;
            #pragma unroll
            for (int nf = 0; nf < 8; ++nf) {
                mc0 = fmaxf(mc0, fmaxf(c[nf][0], c[nf][1]));
                mc1 = fmaxf(mc1, fmaxf(c[nf][2], c[nf][3]));
            }
            mc0 = fmaxf(mc0, __shfl_xor_sync(0xffffffffu, mc0, 1));
            mc0 = fmaxf(mc0, __shfl_xor_sync(0xffffffffu, mc0, 2));
            mc1 = fmaxf(mc1, __shfl_xor_sync(0xffffffffu, mc1, 1));
            mc1 = fmaxf(mc1, __shfl_xor_sync(0xffffffffu, mc1, 2));
            float Mn0 = fmaxf(M0, mc0), Mn1 = fmaxf(M1, mc1);
            float al0 = __expf(M0 - Mn0), al1 = __expf(M1 - Mn1);
            M0 = Mn0; M1 = Mn1;
            #pragma unroll
            for (int nf = 0; nf < 4; ++nf) {
                o[nf][0] *= al0; o[nf][1] *= al0;
                o[nf][2] *= al1; o[nf][3] *= al1;
            }
            float sum0 = 0.f, sum1 = 0.f;
            #pragma unroll
            for (int nf = 0; nf < 8; ++nf) {
                float p0 = __expf(c[nf][0] - M0);
                float p1 = __expf(c[nf][1] - M0);
                float p2 = __expf(c[nf][2] - M1);
                float p3 = __expf(c[nf][3] - M1);
                sum0 += p0 + p1;
                sum1 += p2 + p3;
                c[nf][0] = __uint_as_float(f2tf(p0));
                c[nf][1] = __uint_as_float(f2tf(p1));
                c[nf][2] = __uint_as_float(f2tf(p2));
                c[nf][3] = __uint_as_float(f2tf(p3));
            }
            sum0 += __shfl_xor_sync(0xffffffffu, sum0, 1);
            sum0 += __shfl_xor_sync(0xffffffffu, sum0, 2);
            sum1 += __shfl_xor_sync(0xffffffffu, sum1, 1);
            sum1 += __shfl_xor_sync(0xffffffffu, sum1, 2);
            l0 = l0 * al0 + sum0;
            l1 = l1 * al1 + sum1;
        }

        // ---- P @ V: shuffle P into A-fragments, accumulate O ----
        {
            const unsigned* vb = vbuf + s * VCW;
            #pragma unroll
            for (int ks = 0; ks < 8; ++ks) {
                float v00 = __shfl_sync(0xffffffffu, c[ks][0], s1);
                float v01 = __shfl_sync(0xffffffffu, c[ks][1], s1);
                float v10 = __shfl_sync(0xffffffffu, c[ks][2], s1);
                float v11 = __shfl_sync(0xffffffffu, c[ks][3], s1);
                float w00 = __shfl_sync(0xffffffffu, c[ks][0], s2);
                float w01 = __shfl_sync(0xffffffffu, c[ks][1], s2);
                float w10 = __shfl_sync(0xffffffffu, c[ks][2], s2);
                float w11 = __shfl_sync(0xffffffffu, c[ks][3], s2);
                unsigned a[4];
                a[0] = __float_as_uint(esel ? v01 : v00);
                a[1] = __float_as_uint(esel ? v11 : v10);
                a[2] = __float_as_uint(esel ? w01 : w00);
                a[3] = __float_as_uint(esel ? w11 : w10);
                #pragma unroll
                for (int nf = 0; nf < 4; ++nf) {
                    unsigned bf[2];
                    int bi = (nf * 8 + grp) * 68 + ks * 8 + qid;
                    bf[0] = vb[bi];
                    bf[1] = vb[bi + 4];
                    mma_tf32(o[nf], a, bf);
                }
            }
        }
        __syncthreads();
    }

    // ---- epilogue ----
    {
        float inv0 = 1.0f / l0, inv1 = 1.0f / l1;
        float* op = outp + ((size_t)b * NQ + i0 + warp * 16 + grp) * DIMC
                         + h * DH + qid * 2;
        #pragma unroll
        for (int nf = 0; nf < 4; ++nf) {
            float2 r0, r1;
            r0.x = o[nf][0] * inv0; r0.y = o[nf][1] * inv0;
            r1.x = o[nf][2] * inv1; r1.y = o[nf][3] * inv1;
            *(float2*)(op + nf * 8)            = r0;
            *(float2*)(op + 8 * DIMC + nf * 8) = r1;
        }
    }
}

// ---------------- launcher ----------------
extern "C" void kernel_launch(void* const* d_in, const int* in_sizes, int n_in,
                              void* d_out, int out_size)
{
    (void)in_sizes; (void)n_in; (void)out_size;
    const float* q_w    = (const float*)d_in[0];
    const float* kv_w   = (const float*)d_in[1];
    const float* q_W    = (const float*)d_in[2];
    const float* q_b    = (const float*)d_in[3];
    const float* kv_W   = (const float*)d_in[4];
    const float* kv_b   = (const float*)d_in[5];
    const float* proj_W = (const float*)d_in[6];
    const float* proj_b = (const float*)d_in[7];
    const float* btab   = (const float*)d_in[8];
    const int*   ridx   = (const int*)d_in[9];
    float* out = (float*)d_out;

    float *gq, *gkv, *gb, *ga;
    cudaGetSymbolAddress((void**)&gq,  g_q);
    cudaGetSymbolAddress((void**)&gkv, g_kv);
    cudaGetSymbolAddress((void**)&gb,  g_bias);
    cudaGetSymbolAddress((void**)&ga,  g_att);

    cudaFuncSetAttribute(attn_kernel,
                         cudaFuncAttributeMaxDynamicSharedMemorySize, ATT_SMEM);

    // 1) relative-position bias gather -> (H, Nq, Nk)
    bias_gather_kernel<<<(NQ * NK) / 256, 256>>>(btab, ridx, gb);

    // 2) kv projection: (B*Nk,256) @ (256,512) + b   [tf32 tensor cores]
    tf32_gemm_bias_kernel<<<dim3(512 / 128, (NB * NK) / 128), 256>>>(
        kv_w, kv_W, kv_b, gkv, 512, 1.0f);

    // 3) q projection (pre-scaled by Dh^-0.5): (B*Nq,256) @ (256,256) + b
    tf32_gemm_bias_kernel<<<dim3(256 / 128, (NB * NQ) / 128), 256>>>(
        q_w, q_W, q_b, gq, 256, 0.17677669529663687f);

    // 4) flash attention (tensor cores, online softmax)
    attn_kernel<<<dim3(NQ / 128, HEADS, NB), 256, ATT_SMEM>>>(gq, gkv, gb, ga);

    // 5) output projection: (B*Nq,256) @ (256,256) + b
    tf32_gemm_bias_kernel<<<dim3(256 / 128, (NB * NQ) / 128), 256>>>(
        ga, proj_W, proj_b, out, 256, 1.0f);
}